// round 5
// baseline (speedup 1.0000x reference)
#include <cuda_runtime.h>
#include <cstddef>
#include <cstdint>

#define NN 20000
#define NE 200000
#define NG 128

// ---------------- scratch (device globals) ----------------------------------
__device__ float g_n1[(size_t)NN * 256];
__device__ float g_e1[(size_t)NE * 256];
__device__ float g_g1[(size_t)NG * 256];
__device__ float g_emid[(size_t)NE * 256];
__device__ float g_nin[(size_t)NN * 768];
__device__ float g_nmid[(size_t)NN * 256];
__device__ float g_gin[(size_t)NG * 768];
__device__ float g_gmid[(size_t)NG * 256];
__device__ float g_e2n[(size_t)NN * 256];
#define OFF_E2G 0
#define OFF_N2G 32768
#define OFF_NCNT 65536
#define OFF_GCE 85536
#define OFF_GCN 85664
#define SMALL_N 85792
__device__ float g_small[SMALL_N];
__device__ float g_wr[1048576];   // all 9 weights, tf32-rounded

__device__ __forceinline__ float ssp(float x) {
    return fmaxf(x, 0.0f) + log1pf(__expf(-fabsf(x))) - 0.69314718055994531f;
}
__device__ __forceinline__ uint32_t f2tf32(float f) {
    uint32_t r;
    asm("cvt.rna.tf32.f32 %0, %1;" : "=r"(r) : "f"(f));
    return r;
}
__device__ __forceinline__ float rtf(float f) {
    return __uint_as_float(f2tf32(f));
}
__device__ __forceinline__ void mma_tf32(float* c,
    uint32_t a0, uint32_t a1, uint32_t a2, uint32_t a3,
    uint32_t b0, uint32_t b1)
{
    asm volatile(
        "mma.sync.aligned.m16n8k8.row.col.f32.tf32.tf32.f32 "
        "{%0,%1,%2,%3},{%4,%5,%6,%7},{%8,%9},{%0,%1,%2,%3};\n"
        : "+f"(c[0]), "+f"(c[1]), "+f"(c[2]), "+f"(c[3])
        : "r"(a0), "r"(a1), "r"(a2), "r"(a3), "r"(b0), "r"(b1));
}
__device__ __forceinline__ void cp16(uint32_t saddr, const void* g) {
    asm volatile("cp.async.cg.shared.global [%0], [%1], 16;\n"
                 :: "r"(saddr), "l"(g));
}
__device__ __forceinline__ void ldsm4(uint32_t& r0, uint32_t& r1,
                                      uint32_t& r2, uint32_t& r3, uint32_t a) {
    asm volatile("ldmatrix.sync.aligned.m8n8.x4.shared.b16 {%0,%1,%2,%3},[%4];\n"
                 : "=r"(r0), "=r"(r1), "=r"(r2), "=r"(r3) : "r"(a));
}

// ---------------- zero fill --------------------------------------------------
__global__ void zero_kernel(float* __restrict__ p, int n) {
    int i = blockIdx.x * blockDim.x + threadIdx.x;
    if (i < n) p[i] = 0.0f;
}

// ---------------- round all weights into g_wr --------------------------------
struct WSrc { const float* p[9]; };
#define WO0 0
#define WO1 65536
#define WO2 131072
#define WO3 196608
#define WO4 458752
#define WO5 655360
#define WO6 851968
#define WO7 917504
#define WO8 983040
__global__ __launch_bounds__(256) void round_weights(WSrc ws) {
    int f = (blockIdx.x * 256 + threadIdx.x) * 4;
    if (f >= 1048576) return;
    const float* sp; int base;
    if      (f < WO1) { sp = ws.p[0]; base = WO0; }
    else if (f < WO2) { sp = ws.p[1]; base = WO1; }
    else if (f < WO3) { sp = ws.p[2]; base = WO2; }
    else if (f < WO4) { sp = ws.p[3]; base = WO3; }
    else if (f < WO5) { sp = ws.p[4]; base = WO4; }
    else if (f < WO6) { sp = ws.p[5]; base = WO5; }
    else if (f < WO7) { sp = ws.p[6]; base = WO6; }
    else if (f < WO8) { sp = ws.p[7]; base = WO7; }
    else              { sp = ws.p[8]; base = WO8; }
    float4 v = *(const float4*)(sp + (f - base));
    v.x = rtf(v.x); v.y = rtf(v.y); v.z = rtf(v.z); v.w = rtf(v.w);
    *(float4*)(g_wr + f) = v;
}

// ---------------- main GEMM: C[M,256] = ssp(A @ W^T) variants ----------------
// Block 128x128xK (grid.x = 2 n-blocks). 8 warps, warp tile 32x64 (4m x 2n).
// ldmatrix.x4 fragments from XOR-swizzled smem, cp.async double buffer,
// 2 CTAs/SM. MODE1 = fused edge gather (K=1024). SC1 = edge scatter fused,
// SC2 = node scatter fused. ROUND = store tf32-rounded. ADD = +R residual.
// Stage: A[128x16] at 0, W[128x16] at 8192B; stage stride 16384B.

template <int MODE, int ADD, int ROUND, int SC>
__global__ __launch_bounds__(256, 2) void gemm_k(
    const float* __restrict__ A, const float* __restrict__ W,
    const float* __restrict__ R, float* __restrict__ C,
    int M, int K,
    const int* __restrict__ src, const int* __restrict__ dst,
    const int* __restrict__ batch)
{
    __shared__ __align__(1024) float sm[8192];
    const int tid = threadIdx.x;
    const int m0 = blockIdx.y * 128;
    const int n0 = blockIdx.x * 128;
    const uint32_t smb = (uint32_t)__cvta_generic_to_shared(sm);

    // ---- loader: threads 0-127 load A rows, 128-255 load W rows (1 row each)
    const int lrow = tid & 127;
    const int ls = (lrow >> 1) & 3;
    uint32_t st0, st1, st2, st3;
    {
        uint32_t base = smb + (uint32_t)(lrow * 64) + ((tid < 128) ? 0u : 8192u);
        st0 = base + (uint32_t)((0 ^ ls) << 4);
        st1 = base + (uint32_t)((1 ^ ls) << 4);
        st2 = base + (uint32_t)((2 ^ ls) << 4);
        st3 = base + (uint32_t)((3 ^ ls) << 4);
    }
    const float* gRow = nullptr;
    const float* gp0 = nullptr; const float* gp1 = nullptr;
    const float* gp2 = nullptr; const float* gp3 = nullptr;
    if (tid < 128) {
        if (MODE == 0) {
            int r = min(m0 + lrow, M - 1);
            gRow = A + (size_t)r * K;
        } else {
            int e = min(m0 + lrow, NE - 1);
            int s_ = src[e], d_ = dst[e], b_ = batch[s_];
            gp0 = g_n1 + (size_t)s_ * 256;
            gp1 = g_n1 + (size_t)d_ * 256;
            gp2 = g_e1 + (size_t)e * 256;
            gp3 = g_g1 + (size_t)b_ * 256;
        }
    } else {
        gRow = W + (size_t)(n0 + lrow) * K;
    }

    auto load_tile = [&](int kt, int stg) {
        uint32_t so = (uint32_t)stg * 16384u;
        const float* p;
        if (MODE == 1 && tid < 128) {
            int sg = kt >> 4;
            const float* b = (sg == 0) ? gp0 : (sg == 1) ? gp1
                           : (sg == 2) ? gp2 : gp3;
            p = b + (kt & 15) * 16;
        } else {
            p = gRow + kt * 16;
        }
        cp16(st0 + so, p);
        cp16(st1 + so, p + 4);
        cp16(st2 + so, p + 8);
        cp16(st3 + so, p + 12);
        asm volatile("cp.async.commit_group;\n" ::: "memory");
    };

    // ---- compute mapping: warp tile 32x64, warps (warp&3)=m, (warp>>2)=n
    const int lane = tid & 31, warp = tid >> 5;
    const int wm = (warp & 3) * 32;
    const int wn = (warp >> 2) * 64;
    const int gid = lane >> 2, tig = lane & 3;

    const int arow = wm + (lane & 15);
    const uint32_t aBase = smb + (uint32_t)(arow * 64)
                         + ((((uint32_t)arow >> 1) & 3u) << 4);
    const uint32_t hA = (uint32_t)((lane >> 4) & 1) << 4;
    const int brow = wn + ((lane >> 4) & 1) * 8 + (lane & 7);
    const uint32_t bBase = smb + 8192u + (uint32_t)(brow * 64)
                         + ((((uint32_t)brow >> 1) & 3u) << 4);
    const uint32_t hB = (uint32_t)((lane >> 3) & 1) << 4;

    float acc[2][8][4];
#pragma unroll
    for (int mt = 0; mt < 2; mt++)
#pragma unroll
        for (int nt = 0; nt < 8; nt++)
#pragma unroll
            for (int i = 0; i < 4; i++) acc[mt][nt][i] = 0.0f;

    const int KT = K / 16;
    load_tile(0, 0);

    for (int kt = 0; kt < KT; kt++) {
        asm volatile("cp.async.wait_group 0;\n" ::: "memory");
        __syncthreads();
        if (kt + 1 < KT) load_tile(kt + 1, (kt + 1) & 1);
        const uint32_t so = (uint32_t)(kt & 1) * 16384u;

#pragma unroll
        for (int ks = 0; ks < 2; ks++) {
            const uint32_t kxA = ((uint32_t)(ks << 5)) | hA;
            const uint32_t kxB = ((uint32_t)(ks << 5)) | hB;
            uint32_t a[2][4];
#pragma unroll
            for (int mt = 0; mt < 2; mt++)
                ldsm4(a[mt][0], a[mt][1], a[mt][2], a[mt][3],
                      (aBase + so + (uint32_t)(mt * 1024)) ^ kxA);
            uint32_t b0[8], b1[8];
#pragma unroll
            for (int g = 0; g < 4; g++)
                ldsm4(b0[2 * g], b1[2 * g], b0[2 * g + 1], b1[2 * g + 1],
                      (bBase + so + (uint32_t)(g * 1024)) ^ kxB);
#pragma unroll
            for (int mt = 0; mt < 2; mt++)
#pragma unroll
                for (int nt = 0; nt < 8; nt++)
                    mma_tf32(acc[mt][nt], a[mt][0], a[mt][1], a[mt][2],
                             a[mt][3], b0[nt], b1[nt]);
        }
        __syncthreads();
    }

    // ---- epilogue
    int* sdst = (int*)sm;
    int* sbt = ((int*)sm) + 128;
    if (SC) {
        if (tid < 128) {
            int e = min(m0 + tid, M - 1);
            if (SC == 1) { sdst[tid] = dst[e]; sbt[tid] = batch[src[e]]; }
            else sbt[tid] = batch[e];
        }
        __syncthreads();
    }

#pragma unroll
    for (int mt = 0; mt < 2; mt++) {
#pragma unroll
        for (int half = 0; half < 2; half++) {
            int r = wm + mt * 16 + half * 8 + gid;
            int gr = m0 + r;
            if (gr >= M) continue;
#pragma unroll
            for (int nt = 0; nt < 8; nt++) {
                int col = n0 + wn + nt * 8 + tig * 2;
                float o0 = ssp(acc[mt][nt][half * 2 + 0]);
                float o1 = ssp(acc[mt][nt][half * 2 + 1]);
                if (SC == 1) {
                    atomicAdd(&g_e2n[(size_t)sdst[r] * 256 + col], o0);
                    atomicAdd(&g_e2n[(size_t)sdst[r] * 256 + col + 1], o1);
                    atomicAdd(&g_small[OFF_E2G + sbt[r] * 256 + col], o0);
                    atomicAdd(&g_small[OFF_E2G + sbt[r] * 256 + col + 1], o1);
                } else if (SC == 2) {
                    atomicAdd(&g_small[OFF_N2G + sbt[r] * 256 + col], o0);
                    atomicAdd(&g_small[OFF_N2G + sbt[r] * 256 + col + 1], o1);
                }
                if (ADD) {
                    float2 rv = *(const float2*)&R[(size_t)gr * 256 + col];
                    o0 += rv.x; o1 += rv.y;
                }
                if (ROUND) { o0 = rtf(o0); o1 = rtf(o1); }
                *(float2*)&C[(size_t)gr * 256 + col] = make_float2(o0, o1);
            }
            if (SC && blockIdx.x == 0 && wn == 0 && tig == 0) {
                if (SC == 1) {
                    atomicAdd(&g_small[OFF_NCNT + sdst[r]], 1.0f);
                    atomicAdd(&g_small[OFF_GCE + sbt[r]], 1.0f);
                } else {
                    atomicAdd(&g_small[OFF_GCN + sbt[r]], 1.0f);
                }
            }
        }
    }
}

// ---------------- node_in = [n1, e2n_mean, g1[batch]] (tf32-rounded) --------
__global__ __launch_bounds__(192) void build_node_in(const int* __restrict__ batch)
{
    int v = blockIdx.x;
    int t = threadIdx.x;
    int seg = t / 64, w = t % 64;
    float4 val;
    if (seg == 0) {
        val = ((const float4*)g_n1)[(size_t)v * 64 + w];
    } else if (seg == 1) {
        float inv = 1.0f / fmaxf(g_small[OFF_NCNT + v], 1.0f);
        float4 sv = ((const float4*)g_e2n)[(size_t)v * 64 + w];
        val = make_float4(rtf(sv.x * inv), rtf(sv.y * inv),
                          rtf(sv.z * inv), rtf(sv.w * inv));
    } else {
        int b = batch[v];
        val = ((const float4*)g_g1)[(size_t)b * 64 + w];
    }
    ((float4*)g_nin)[(size_t)v * 192 + t] = val;
}

// ---------------- glob_in = [n2g_mean, e2g_mean, g1] (tf32-rounded) ---------
__global__ __launch_bounds__(192) void build_glob_in()
{
    int gi = blockIdx.x;
    int t = threadIdx.x;
    int seg = t / 64, w = t % 64;
    float4 val;
    if (seg == 0) {
        float inv = 1.0f / fmaxf(g_small[OFF_GCN + gi], 1.0f);
        float4 sv = *(const float4*)&g_small[OFF_N2G + gi * 256 + w * 4];
        val = make_float4(rtf(sv.x * inv), rtf(sv.y * inv),
                          rtf(sv.z * inv), rtf(sv.w * inv));
    } else if (seg == 1) {
        float inv = 1.0f / fmaxf(g_small[OFF_GCE + gi], 1.0f);
        float4 sv = *(const float4*)&g_small[OFF_E2G + gi * 256 + w * 4];
        val = make_float4(rtf(sv.x * inv), rtf(sv.y * inv),
                          rtf(sv.z * inv), rtf(sv.w * inv));
    } else {
        val = ((const float4*)g_g1)[(size_t)gi * 64 + w];
    }
    ((float4*)g_gin)[(size_t)gi * 192 + t] = val;
}

// ---------------- host side ---------------------------------------------------
template <typename T>
static T* sym(const void* symbol) {
    void* p = nullptr;
    cudaGetSymbolAddress(&p, symbol);
    return (T*)p;
}

extern "C" void kernel_launch(void* const* d_in, const int* in_sizes, int n_in,
                              void* d_out, int out_size) {
    const float* node_feats = (const float*)d_in[0];
    const float* edge_feats = (const float*)d_in[1];
    const float* glob_feats = (const float*)d_in[2];
    const int*   edge_index = (const int*)d_in[3];
    const int*   batch      = (const int*)d_in[4];

    const int* src = edge_index;
    const int* dst = edge_index + NE;

    float* out = (float*)d_out;
    float* out_n = out;
    float* out_e = out + (size_t)NN * 256;
    float* out_g = out + (size_t)(NN + NE) * 256;

    float* p_n1   = sym<float>(g_n1);
    float* p_e1   = sym<float>(g_e1);
    float* p_g1   = sym<float>(g_g1);
    float* p_emid = sym<float>(g_emid);
    float* p_nin  = sym<float>(g_nin);
    float* p_nmid = sym<float>(g_nmid);
    float* p_gin  = sym<float>(g_gin);
    float* p_gmid = sym<float>(g_gmid);
    float* p_e2n  = sym<float>(g_e2n);
    float* p_small = sym<float>(g_small);
    float* p_wr   = sym<float>(g_wr);

    // zero scatter accumulators
    zero_kernel<<<(NN * 256 + 255) / 256, 256>>>(p_e2n, NN * 256);
    zero_kernel<<<(SMALL_N + 255) / 256, 256>>>(p_small, SMALL_N);

    // round weights once per call
    WSrc ws;
    for (int i = 0; i < 9; i++) ws.p[i] = (const float*)d_in[5 + i];
    round_weights<<<1024, 256>>>(ws);

    // stage 1: input projections + ssp
    gemm_k<0,0,1,0><<<dim3(2, (NN + 127) / 128), 256>>>(node_feats, p_wr + WO0,
        nullptr, p_n1, NN, 256, nullptr, nullptr, nullptr);
    gemm_k<0,0,1,0><<<dim3(2, (NE + 127) / 128), 256>>>(edge_feats, p_wr + WO1,
        nullptr, p_e1, NE, 256, nullptr, nullptr, nullptr);
    gemm_k<0,0,1,0><<<dim3(2, 1), 256>>>(glob_feats, p_wr + WO2,
        nullptr, p_g1, NG, 256, nullptr, nullptr, nullptr);

    // EdgeModel: gather fused in, scatter (e2n/e2g/counts) fused out
    gemm_k<1,0,1,1><<<dim3(2, (NE + 127) / 128), 256>>>(nullptr, p_wr + WO3,
        nullptr, p_emid, NE, 1024, src, dst, batch);

    // NodeModel
    build_node_in<<<NN, 192>>>(batch);
    gemm_k<0,0,1,2><<<dim3(2, (NN + 127) / 128), 256>>>(p_nin, p_wr + WO4,
        nullptr, p_nmid, NN, 768, nullptr, nullptr, batch);

    // GlobalModel
    build_glob_in<<<NG, 192>>>();
    gemm_k<0,0,1,0><<<dim3(2, 1), 256>>>(p_gin, p_wr + WO5,
        nullptr, p_gmid, NG, 768, nullptr, nullptr, nullptr);

    // output projections + ssp + residual (full-precision outputs)
    gemm_k<0,1,0,0><<<dim3(2, (NN + 127) / 128), 256>>>(p_nmid, p_wr + WO6,
        node_feats, out_n, NN, 256, nullptr, nullptr, nullptr);
    gemm_k<0,1,0,0><<<dim3(2, (NE + 127) / 128), 256>>>(p_emid, p_wr + WO7,
        edge_feats, out_e, NE, 256, nullptr, nullptr, nullptr);
    gemm_k<0,1,0,0><<<dim3(2, 1), 256>>>(p_gmid, p_wr + WO8,
        glob_feats, out_g, NG, 256, nullptr, nullptr, nullptr);
}

// round 6
// speedup vs baseline: 2.0317x; 2.0317x over previous
#include <cuda_runtime.h>
#include <cuda.h>
#include <cstddef>
#include <cstdint>

#define NN 20000
#define NE 200000
#define NG 128

// ---------------- scratch (device globals) ----------------------------------
__device__ __align__(256) float g_n1[(size_t)NN * 256];
__device__ __align__(256) float g_e1[(size_t)NE * 256];
__device__ __align__(256) float g_g1[(size_t)NG * 256];
__device__ __align__(256) float g_p1[(size_t)NN * 256];
__device__ __align__(256) float g_p2[(size_t)NN * 256];
__device__ __align__(256) float g_p3[(size_t)NE * 256];
__device__ __align__(256) float g_p4[(size_t)NG * 256];
__device__ __align__(256) float g_emid[(size_t)NE * 256];
__device__ __align__(256) float g_nin[(size_t)NN * 768];
__device__ __align__(256) float g_nmid[(size_t)NN * 256];
__device__ __align__(256) float g_gin[(size_t)NG * 768];
__device__ __align__(256) float g_gmid[(size_t)NG * 256];
__device__ __align__(256) float g_e2n[(size_t)NN * 256];
#define OFF_E2G 0
#define OFF_N2G 32768
#define OFF_NCNT 65536
#define OFF_GCE 85536
#define OFF_GCN 85664
#define SMALL_N 85792
__device__ float g_small[SMALL_N];
__device__ __align__(256) float g_wr[1048576];   // all 9 weights, tf32-rounded

// ---------------- device helpers ---------------------------------------------
__device__ __forceinline__ float ssp(float x) {
    return fmaxf(x, 0.0f) + log1pf(__expf(-fabsf(x))) - 0.69314718055994531f;
}
__device__ __forceinline__ uint32_t f2tf32(float f) {
    uint32_t r;
    asm("cvt.rna.tf32.f32 %0, %1;" : "=r"(r) : "f"(f));
    return r;
}
__device__ __forceinline__ float rtf(float f) {
    return __uint_as_float(f2tf32(f));
}
__device__ __forceinline__ void mma_tf32(float* c,
    uint32_t a0, uint32_t a1, uint32_t a2, uint32_t a3,
    uint32_t b0, uint32_t b1)
{
    asm volatile(
        "mma.sync.aligned.m16n8k8.row.col.f32.tf32.tf32.f32 "
        "{%0,%1,%2,%3},{%4,%5,%6,%7},{%8,%9},{%0,%1,%2,%3};\n"
        : "+f"(c[0]), "+f"(c[1]), "+f"(c[2]), "+f"(c[3])
        : "r"(a0), "r"(a1), "r"(a2), "r"(a3), "r"(b0), "r"(b1));
}
__device__ __forceinline__ void ldsm4(uint32_t& r0, uint32_t& r1,
                                      uint32_t& r2, uint32_t& r3, uint32_t a) {
    asm volatile("ldmatrix.sync.aligned.m8n8.x4.shared.b16 {%0,%1,%2,%3},[%4];\n"
                 : "=r"(r0), "=r"(r1), "=r"(r2), "=r"(r3) : "r"(a));
}
__device__ __forceinline__ void red4(float* p, float a, float b, float c, float d) {
    asm volatile("red.global.add.v4.f32 [%0], {%1,%2,%3,%4};"
                 :: "l"(p), "f"(a), "f"(b), "f"(c), "f"(d) : "memory");
}
__device__ __forceinline__ void mbar_init(uint32_t mbar, uint32_t cnt) {
    asm volatile("mbarrier.init.shared.b64 [%0], %1;" :: "r"(mbar), "r"(cnt) : "memory");
}
__device__ __forceinline__ void mbar_expect(uint32_t mbar, uint32_t bytes) {
    asm volatile("mbarrier.arrive.expect_tx.shared.b64 _, [%0], %1;"
                 :: "r"(mbar), "r"(bytes) : "memory");
}
__device__ __forceinline__ void mbar_wait(uint32_t mbar, uint32_t parity) {
    asm volatile(
        "{\n\t.reg .pred P;\n\t"
        "W_%=:\n\t"
        "mbarrier.try_wait.parity.acquire.cta.shared::cta.b64 P, [%0], %1, 10000000;\n\t"
        "@P bra.uni D_%=;\n\t"
        "bra.uni W_%=;\n\t"
        "D_%=:\n\t}"
        :: "r"(mbar), "r"(parity) : "memory");
}
__device__ __forceinline__ void tma2d(uint32_t saddr, const CUtensorMap* tm,
                                      int cx, int cy, uint32_t mbar) {
    asm volatile(
        "cp.async.bulk.tensor.2d.shared::cta.global.tile.mbarrier::complete_tx::bytes "
        "[%0], [%1, {%2, %3}], [%4];"
        :: "r"(saddr), "l"(tm), "r"(cx), "r"(cy), "r"(mbar) : "memory");
}

// ---------------- zero fill ----------------------------------------------------
__global__ void zero_kernel(float* __restrict__ p, int n) {
    int i = blockIdx.x * blockDim.x + threadIdx.x;
    if (i < n) p[i] = 0.0f;
}

// ---------------- round all weights into g_wr ----------------------------------
struct WSrc { const float* p[9]; };
#define WO0 0
#define WO1 65536
#define WO2 131072
#define WO3 196608
#define WO4 458752
#define WO5 655360
#define WO6 851968
#define WO7 917504
#define WO8 983040
__global__ __launch_bounds__(256) void round_weights(WSrc ws) {
    int f = (blockIdx.x * 256 + threadIdx.x) * 4;
    if (f >= 1048576) return;
    const float* sp; int base;
    if      (f < WO1) { sp = ws.p[0]; base = WO0; }
    else if (f < WO2) { sp = ws.p[1]; base = WO1; }
    else if (f < WO3) { sp = ws.p[2]; base = WO2; }
    else if (f < WO4) { sp = ws.p[3]; base = WO3; }
    else if (f < WO5) { sp = ws.p[4]; base = WO4; }
    else if (f < WO6) { sp = ws.p[5]; base = WO5; }
    else if (f < WO7) { sp = ws.p[6]; base = WO6; }
    else if (f < WO8) { sp = ws.p[7]; base = WO7; }
    else              { sp = ws.p[8]; base = WO8; }
    float4 v = *(const float4*)(sp + (f - base));
    v.x = rtf(v.x); v.y = rtf(v.y); v.z = rtf(v.z); v.w = rtf(v.w);
    *(float4*)(g_wr + f) = v;
}

// ---------------- TMA-fed GEMM: C[M,256] = [ssp](A[M,K] @ W^T) [+R] ------------
// Block 128x128 (grid.x = 2 n-blocks), 8 warps, warp tile 32x64 (4m x 2n).
// TBK=32 (128B rows, SW128 swizzle), 3-stage TMA pipeline, mma.sync tf32.
// ACT: apply ssp. ADD: +R residual. ROUND: store tf32-rounded.
// SC=2: fused n->graph scatter (uses batch).
#define STG_BYTES 32768u
#define SMEMSZ (3 * 32768 + 1024)

template <int ACT, int ADD, int ROUND, int SC>
__global__ __launch_bounds__(256, 2) void gemm_t(
    const __grid_constant__ CUtensorMap tmA,
    const __grid_constant__ CUtensorMap tmW,
    const float* __restrict__ R, float* __restrict__ C,
    int M, int K, const int* __restrict__ batch)
{
    extern __shared__ float dsm[];
    __shared__ __align__(8) uint64_t mbar_s[3];
    uint32_t smb = (uint32_t)__cvta_generic_to_shared(dsm);
    smb = (smb + 1023u) & ~1023u;
    const uint32_t mb = (uint32_t)__cvta_generic_to_shared(mbar_s);

    const int tid = threadIdx.x;
    const int m0 = blockIdx.y * 128;
    const int n0 = blockIdx.x * 128;

    if (tid == 0) {
        mbar_init(mb, 1); mbar_init(mb + 8, 1); mbar_init(mb + 16, 1);
    }
    __syncthreads();

    const int KT = K / 32;
    auto issue = [&](int kt, int s) {
        uint32_t base = smb + (uint32_t)s * STG_BYTES;
        mbar_expect(mb + s * 8, STG_BYTES);
        tma2d(base, &tmA, kt * 32, m0, mb + s * 8);
        tma2d(base + 16384u, &tmW, kt * 32, n0, mb + s * 8);
    };
    if (tid == 0) {
        int pre = KT < 3 ? KT : 3;
        for (int i = 0; i < pre; i++) issue(i, i);
    }

    // ---- fragment addressing (SW128: chunk ^= row&7 within 128B rows)
    const int lane = tid & 31, warp = tid >> 5;
    const int wm = (warp & 3) * 32;
    const int wn = (warp >> 2) * 64;
    const int gid = lane >> 2, tig = lane & 3;
    const int hA = (lane >> 4) & 1;
    const int hB = (lane >> 3) & 1;
    const int arow = wm + (lane & 15);
    const int brow = wn + ((lane >> 4) & 1) * 8 + (lane & 7);
    const uint32_t aAddr = smb + (uint32_t)(arow * 128);
    const uint32_t bAddr = smb + 16384u + (uint32_t)(brow * 128);
    uint32_t cA[4], cB[4];
#pragma unroll
    for (int ks = 0; ks < 4; ks++) {
        cA[ks] = (uint32_t)((((ks * 2 + hA)) ^ (arow & 7)) << 4);
        cB[ks] = (uint32_t)((((ks * 2 + hB)) ^ (brow & 7)) << 4);
    }

    float acc[2][8][4];
#pragma unroll
    for (int mt = 0; mt < 2; mt++)
#pragma unroll
        for (int nt = 0; nt < 8; nt++)
#pragma unroll
            for (int i = 0; i < 4; i++) acc[mt][nt][i] = 0.0f;

    for (int kt = 0; kt < KT; kt++) {
        const int s = kt % 3;
        mbar_wait(mb + s * 8, (uint32_t)((kt / 3) & 1));
        const uint32_t so = (uint32_t)s * STG_BYTES;

#pragma unroll
        for (int ks = 0; ks < 4; ks++) {
            uint32_t a[2][4];
#pragma unroll
            for (int mt = 0; mt < 2; mt++)
                ldsm4(a[mt][0], a[mt][1], a[mt][2], a[mt][3],
                      aAddr + so + (uint32_t)(mt * 2048) + cA[ks]);
            uint32_t b0[8], b1[8];
#pragma unroll
            for (int g = 0; g < 4; g++)
                ldsm4(b0[2 * g], b1[2 * g], b0[2 * g + 1], b1[2 * g + 1],
                      bAddr + so + (uint32_t)(g * 2048) + cB[ks]);
#pragma unroll
            for (int mt = 0; mt < 2; mt++)
#pragma unroll
                for (int nt = 0; nt < 8; nt++)
                    mma_tf32(acc[mt][nt], a[mt][0], a[mt][1], a[mt][2],
                             a[mt][3], b0[nt], b1[nt]);
        }
        __syncthreads();
        if (tid == 0 && kt + 3 < KT) issue(kt + 3, s);
    }

    // ---- epilogue
    int* sbt = (int*)dsm;
    if (SC == 2) {
        if (tid < 128) sbt[tid] = batch[min(m0 + tid, M - 1)];
        __syncthreads();
    }

#pragma unroll
    for (int mt = 0; mt < 2; mt++) {
#pragma unroll
        for (int half = 0; half < 2; half++) {
            int r = wm + mt * 16 + half * 8 + gid;
            int gr = m0 + r;
            if (gr >= M) continue;
#pragma unroll
            for (int nt = 0; nt < 8; nt++) {
                int col = n0 + wn + nt * 8 + tig * 2;
                float o0 = acc[mt][nt][half * 2 + 0];
                float o1 = acc[mt][nt][half * 2 + 1];
                if (ACT) { o0 = ssp(o0); o1 = ssp(o1); }
                if (SC == 2) {
                    atomicAdd(&g_small[OFF_N2G + sbt[r] * 256 + col], o0);
                    atomicAdd(&g_small[OFF_N2G + sbt[r] * 256 + col + 1], o1);
                }
                if (ADD) {
                    float2 rv = *(const float2*)&R[(size_t)gr * 256 + col];
                    o0 += rv.x; o1 += rv.y;
                }
                if (ROUND) { o0 = rtf(o0); o1 = rtf(o1); }
                *(float2*)&C[(size_t)gr * 256 + col] = make_float2(o0, o1);
            }
            if (SC == 2 && blockIdx.x == 0 && wn == 0 && tig == 0)
                atomicAdd(&g_small[OFF_GCN + sbt[r]], 1.0f);
        }
    }
}

// ---------------- edge combine: emid = ssp(P1[s]+P2[d]+P3[e]+P4[b]) + scatter --
__global__ __launch_bounds__(256) void combine_edge(
    const int* __restrict__ src, const int* __restrict__ dst,
    const int* __restrict__ batch)
{
    int e = blockIdx.x * 4 + (threadIdx.x >> 6);
    int t = threadIdx.x & 63;
    int s = src[e], d = dst[e], b = batch[s];
    float4 p1 = ((const float4*)g_p1)[(size_t)s * 64 + t];
    float4 p2 = ((const float4*)g_p2)[(size_t)d * 64 + t];
    float4 p3 = ((const float4*)g_p3)[(size_t)e * 64 + t];
    float4 p4 = ((const float4*)g_p4)[(size_t)b * 64 + t];
    float o0 = ssp(p1.x + p2.x + p3.x + p4.x);
    float o1 = ssp(p1.y + p2.y + p3.y + p4.y);
    float o2 = ssp(p1.z + p2.z + p3.z + p4.z);
    float o3 = ssp(p1.w + p2.w + p3.w + p4.w);
    red4(&g_e2n[(size_t)d * 256 + t * 4], o0, o1, o2, o3);
    red4(&g_small[OFF_E2G + b * 256 + t * 4], o0, o1, o2, o3);
    if (t == 0) {
        atomicAdd(&g_small[OFF_NCNT + d], 1.0f);
        atomicAdd(&g_small[OFF_GCE + b], 1.0f);
    }
    float4 ov = make_float4(rtf(o0), rtf(o1), rtf(o2), rtf(o3));
    ((float4*)g_emid)[(size_t)e * 64 + t] = ov;
}

// ---------------- node_in = [n1, e2n_mean, g1[batch]] (tf32-rounded) -----------
__global__ __launch_bounds__(192) void build_node_in(const int* __restrict__ batch)
{
    int v = blockIdx.x;
    int t = threadIdx.x;
    int seg = t / 64, w = t % 64;
    float4 val;
    if (seg == 0) {
        val = ((const float4*)g_n1)[(size_t)v * 64 + w];
    } else if (seg == 1) {
        float inv = 1.0f / fmaxf(g_small[OFF_NCNT + v], 1.0f);
        float4 sv = ((const float4*)g_e2n)[(size_t)v * 64 + w];
        val = make_float4(rtf(sv.x * inv), rtf(sv.y * inv),
                          rtf(sv.z * inv), rtf(sv.w * inv));
    } else {
        int b = batch[v];
        val = ((const float4*)g_g1)[(size_t)b * 64 + w];
    }
    ((float4*)g_nin)[(size_t)v * 192 + t] = val;
}

// ---------------- glob_in = [n2g_mean, e2g_mean, g1] (tf32-rounded) ------------
__global__ __launch_bounds__(192) void build_glob_in()
{
    int gi = blockIdx.x;
    int t = threadIdx.x;
    int seg = t / 64, w = t % 64;
    float4 val;
    if (seg == 0) {
        float inv = 1.0f / fmaxf(g_small[OFF_GCN + gi], 1.0f);
        float4 sv = *(const float4*)&g_small[OFF_N2G + gi * 256 + w * 4];
        val = make_float4(rtf(sv.x * inv), rtf(sv.y * inv),
                          rtf(sv.z * inv), rtf(sv.w * inv));
    } else if (seg == 1) {
        float inv = 1.0f / fmaxf(g_small[OFF_GCE + gi], 1.0f);
        float4 sv = *(const float4*)&g_small[OFF_E2G + gi * 256 + w * 4];
        val = make_float4(rtf(sv.x * inv), rtf(sv.y * inv),
                          rtf(sv.z * inv), rtf(sv.w * inv));
    } else {
        val = ((const float4*)g_g1)[(size_t)gi * 64 + w];
    }
    ((float4*)g_gin)[(size_t)gi * 192 + t] = val;
}

// ---------------- host side -----------------------------------------------------
template <typename T>
static T* sym(const void* symbol) {
    void* p = nullptr;
    cudaGetSymbolAddress(&p, symbol);
    return (T*)p;
}

typedef CUresult (*PFN_encode)(
    CUtensorMap*, CUtensorMapDataType, cuuint32_t, void*,
    const cuuint64_t*, const cuuint64_t*, const cuuint32_t*, const cuuint32_t*,
    CUtensorMapInterleave, CUtensorMapSwizzle, CUtensorMapL2promotion,
    CUtensorMapFloatOOBfill);

static void enc(PFN_encode fn, CUtensorMap* m, const void* base,
                unsigned long long kElems, unsigned long long rows,
                unsigned long long rowStrideBytes) {
    cuuint64_t dims[2] = {kElems, rows};
    cuuint64_t st[1] = {rowStrideBytes};
    cuuint32_t box[2] = {32u, 128u};
    cuuint32_t es[2] = {1u, 1u};
    fn(m, CU_TENSOR_MAP_DATA_TYPE_FLOAT32, 2, (void*)base, dims, st, box, es,
       CU_TENSOR_MAP_INTERLEAVE_NONE, CU_TENSOR_MAP_SWIZZLE_128B,
       CU_TENSOR_MAP_L2_PROMOTION_L2_128B, CU_TENSOR_MAP_FLOAT_OOB_FILL_NONE);
}

extern "C" void kernel_launch(void* const* d_in, const int* in_sizes, int n_in,
                              void* d_out, int out_size) {
    const float* node_feats = (const float*)d_in[0];
    const float* edge_feats = (const float*)d_in[1];
    const float* glob_feats = (const float*)d_in[2];
    const int*   edge_index = (const int*)d_in[3];
    const int*   batch      = (const int*)d_in[4];

    const int* src = edge_index;
    const int* dst = edge_index + NE;

    float* out = (float*)d_out;
    float* out_n = out;
    float* out_e = out + (size_t)NN * 256;
    float* out_g = out + (size_t)(NN + NE) * 256;

    float* p_n1   = sym<float>(g_n1);
    float* p_e1   = sym<float>(g_e1);
    float* p_g1   = sym<float>(g_g1);
    float* p_p1   = sym<float>(g_p1);
    float* p_p2   = sym<float>(g_p2);
    float* p_p3   = sym<float>(g_p3);
    float* p_p4   = sym<float>(g_p4);
    float* p_emid = sym<float>(g_emid);
    float* p_nin  = sym<float>(g_nin);
    float* p_nmid = sym<float>(g_nmid);
    float* p_gin  = sym<float>(g_gin);
    float* p_gmid = sym<float>(g_gmid);
    float* p_e2n  = sym<float>(g_e2n);
    float* p_small = sym<float>(g_small);
    float* p_wr   = sym<float>(g_wr);

    // driver entry point for tensormap encode (header-only, no -lcuda)
    PFN_encode encfn = nullptr;
    {
        void* fp = nullptr;
        cudaDriverEntryPointQueryResult qr;
        cudaGetDriverEntryPoint("cuTensorMapEncodeTiled", &fp,
                                cudaEnableDefault, &qr);
        encfn = (PFN_encode)fp;
    }

    // ---- tensormaps (A: activations, W: rounded weights)
    CUtensorMap mA_node, mA_edge, mA_glob, mA_n1, mA_e1, mA_g1;
    CUtensorMap mA_nin, mA_gin, mA_nmid, mA_emid, mA_gmid;
    enc(encfn, &mA_node, node_feats, 256, NN, 1024);
    enc(encfn, &mA_edge, edge_feats, 256, NE, 1024);
    enc(encfn, &mA_glob, glob_feats, 256, NG, 1024);
    enc(encfn, &mA_n1, p_n1, 256, NN, 1024);
    enc(encfn, &mA_e1, p_e1, 256, NE, 1024);
    enc(encfn, &mA_g1, p_g1, 256, NG, 1024);
    enc(encfn, &mA_nin, p_nin, 768, NN, 3072);
    enc(encfn, &mA_gin, p_gin, 768, NG, 3072);
    enc(encfn, &mA_nmid, p_nmid, 256, NN, 1024);
    enc(encfn, &mA_emid, p_emid, 256, NE, 1024);
    enc(encfn, &mA_gmid, p_gmid, 256, NG, 1024);

    CUtensorMap mW_n1, mW_e1, mW_g1, mW_p1, mW_p2, mW_p3, mW_p4;
    CUtensorMap mW_nmlp, mW_gmlp, mW_n2, mW_e2, mW_g2;
    enc(encfn, &mW_n1, p_wr + WO0, 256, 256, 1024);
    enc(encfn, &mW_e1, p_wr + WO1, 256, 256, 1024);
    enc(encfn, &mW_g1, p_wr + WO2, 256, 256, 1024);
    enc(encfn, &mW_p1, p_wr + WO3 + 0,   256, 256, 4096);
    enc(encfn, &mW_p2, p_wr + WO3 + 256, 256, 256, 4096);
    enc(encfn, &mW_p3, p_wr + WO3 + 512, 256, 256, 4096);
    enc(encfn, &mW_p4, p_wr + WO3 + 768, 256, 256, 4096);
    enc(encfn, &mW_nmlp, p_wr + WO4, 768, 256, 3072);
    enc(encfn, &mW_gmlp, p_wr + WO5, 768, 256, 3072);
    enc(encfn, &mW_n2, p_wr + WO6, 256, 256, 1024);
    enc(encfn, &mW_e2, p_wr + WO7, 256, 256, 1024);
    enc(encfn, &mW_g2, p_wr + WO8, 256, 256, 1024);

    cudaFuncSetAttribute(gemm_t<1,0,1,0>, cudaFuncAttributeMaxDynamicSharedMemorySize, SMEMSZ);
    cudaFuncSetAttribute(gemm_t<0,0,0,0>, cudaFuncAttributeMaxDynamicSharedMemorySize, SMEMSZ);
    cudaFuncSetAttribute(gemm_t<1,0,1,2>, cudaFuncAttributeMaxDynamicSharedMemorySize, SMEMSZ);
    cudaFuncSetAttribute(gemm_t<1,1,0,0>, cudaFuncAttributeMaxDynamicSharedMemorySize, SMEMSZ);

    const int BN_N = (NN + 127) / 128;
    const int BN_E = (NE + 127) / 128;

    // zero scatter accumulators
    zero_kernel<<<(NN * 256 + 255) / 256, 256>>>(p_e2n, NN * 256);
    zero_kernel<<<(SMALL_N + 255) / 256, 256>>>(p_small, SMALL_N);

    // round weights
    WSrc ws;
    for (int i = 0; i < 9; i++) ws.p[i] = (const float*)d_in[5 + i];
    round_weights<<<1024, 256>>>(ws);

    // stage 1: input projections + ssp (rounded outputs)
    gemm_t<1,0,1,0><<<dim3(2, BN_N), 256, SMEMSZ>>>(mA_node, mW_n1, nullptr, p_n1, NN, 256, nullptr);
    gemm_t<1,0,1,0><<<dim3(2, BN_E), 256, SMEMSZ>>>(mA_edge, mW_e1, nullptr, p_e1, NE, 256, nullptr);
    gemm_t<1,0,1,0><<<dim3(2, 1),    256, SMEMSZ>>>(mA_glob, mW_g1, nullptr, p_g1, NG, 256, nullptr);

    // EdgeModel decomposed: P1..P4 partials (no activation, fp32)
    gemm_t<0,0,0,0><<<dim3(2, BN_N), 256, SMEMSZ>>>(mA_n1, mW_p1, nullptr, p_p1, NN, 256, nullptr);
    gemm_t<0,0,0,0><<<dim3(2, BN_N), 256, SMEMSZ>>>(mA_n1, mW_p2, nullptr, p_p2, NN, 256, nullptr);
    gemm_t<0,0,0,0><<<dim3(2, BN_E), 256, SMEMSZ>>>(mA_e1, mW_p3, nullptr, p_p3, NE, 256, nullptr);
    gemm_t<0,0,0,0><<<dim3(2, 1),    256, SMEMSZ>>>(mA_g1, mW_p4, nullptr, p_p4, NG, 256, nullptr);

    // combine + ssp + scatter (e2n, e2g, counts) + emid
    combine_edge<<<NE / 4, 256>>>(src, dst, batch);

    // NodeModel
    build_node_in<<<NN, 192>>>(batch);
    gemm_t<1,0,1,2><<<dim3(2, BN_N), 256, SMEMSZ>>>(mA_nin, mW_nmlp, nullptr, p_nmid, NN, 768, batch);

    // GlobalModel
    build_glob_in<<<NG, 192>>>();
    gemm_t<1,0,1,0><<<dim3(2, 1), 256, SMEMSZ>>>(mA_gin, mW_gmlp, nullptr, p_gmid, NG, 768, nullptr);

    // output projections + ssp + residual
    gemm_t<1,1,0,0><<<dim3(2, BN_N), 256, SMEMSZ>>>(mA_nmid, mW_n2, node_feats, out_n, NN, 256, nullptr);
    gemm_t<1,1,0,0><<<dim3(2, BN_E), 256, SMEMSZ>>>(mA_emid, mW_e2, edge_feats, out_e, NE, 256, nullptr);
    gemm_t<1,1,0,0><<<dim3(2, 1),    256, SMEMSZ>>>(mA_gmid, mW_g2, glob_feats, out_g, NG, 256, nullptr);
}

// round 7
// speedup vs baseline: 2.5129x; 1.2368x over previous
#include <cuda_runtime.h>
#include <cuda.h>
#include <cuda_bf16.h>
#include <cstddef>
#include <cstdint>

#define NN 20000
#define NE 200000
#define NG 128

// ---------------- scratch (device globals) ----------------------------------
// bf16 activation buffers (GEMM operands)
__device__ __align__(256) __nv_bfloat16 g_bnode[(size_t)NN * 256];
__device__ __align__(256) __nv_bfloat16 g_bedge[(size_t)NE * 256];
__device__ __align__(256) __nv_bfloat16 g_bglob[(size_t)NG * 256];
__device__ __align__(256) __nv_bfloat16 g_bn1[(size_t)NN * 256];
__device__ __align__(256) __nv_bfloat16 g_be1[(size_t)NE * 256];
__device__ __align__(256) __nv_bfloat16 g_bg1[(size_t)NG * 256];
__device__ __align__(256) __nv_bfloat16 g_bnin[(size_t)NN * 768];
__device__ __align__(256) __nv_bfloat16 g_bgin[(size_t)NG * 768];
__device__ __align__(256) __nv_bfloat16 g_bnmid[(size_t)NN * 256];
__device__ __align__(256) __nv_bfloat16 g_bemid[(size_t)NE * 256];
__device__ __align__(256) __nv_bfloat16 g_bgmid[(size_t)NG * 256];
__device__ __align__(256) __nv_bfloat16 g_wb[1048576];   // all 9 weights, bf16
// fp32 partials + scatter accumulators
__device__ __align__(256) float g_p1[(size_t)NN * 256];
__device__ __align__(256) float g_p2[(size_t)NN * 256];
__device__ __align__(256) float g_p3[(size_t)NE * 256];
__device__ __align__(256) float g_p4[(size_t)NG * 256];
__device__ __align__(256) float g_e2n[(size_t)NN * 256];
#define OFF_E2G 0
#define OFF_N2G 32768
#define OFF_NCNT 65536
#define OFF_GCE 85536
#define OFF_GCN 85664
#define SMALL_N 85792
__device__ float g_small[SMALL_N];

// ---------------- device helpers ---------------------------------------------
__device__ __forceinline__ float ssp(float x) {
    return fmaxf(x, 0.0f) + log1pf(__expf(-fabsf(x))) - 0.69314718055994531f;
}
__device__ __forceinline__ void mma_bf16(float* c,
    uint32_t a0, uint32_t a1, uint32_t a2, uint32_t a3,
    uint32_t b0, uint32_t b1)
{
    asm volatile(
        "mma.sync.aligned.m16n8k16.row.col.f32.bf16.bf16.f32 "
        "{%0,%1,%2,%3},{%4,%5,%6,%7},{%8,%9},{%0,%1,%2,%3};\n"
        : "+f"(c[0]), "+f"(c[1]), "+f"(c[2]), "+f"(c[3])
        : "r"(a0), "r"(a1), "r"(a2), "r"(a3), "r"(b0), "r"(b1));
}
__device__ __forceinline__ void ldsm4(uint32_t& r0, uint32_t& r1,
                                      uint32_t& r2, uint32_t& r3, uint32_t a) {
    asm volatile("ldmatrix.sync.aligned.m8n8.x4.shared.b16 {%0,%1,%2,%3},[%4];\n"
                 : "=r"(r0), "=r"(r1), "=r"(r2), "=r"(r3) : "r"(a));
}
__device__ __forceinline__ void red4(float* p, float a, float b, float c, float d) {
    asm volatile("red.global.add.v4.f32 [%0], {%1,%2,%3,%4};"
                 :: "l"(p), "f"(a), "f"(b), "f"(c), "f"(d) : "memory");
}
__device__ __forceinline__ void mbar_init(uint32_t mbar, uint32_t cnt) {
    asm volatile("mbarrier.init.shared.b64 [%0], %1;" :: "r"(mbar), "r"(cnt) : "memory");
}
__device__ __forceinline__ void mbar_expect(uint32_t mbar, uint32_t bytes) {
    asm volatile("mbarrier.arrive.expect_tx.shared.b64 _, [%0], %1;"
                 :: "r"(mbar), "r"(bytes) : "memory");
}
__device__ __forceinline__ void mbar_wait(uint32_t mbar, uint32_t parity) {
    asm volatile(
        "{\n\t.reg .pred P;\n\t"
        "W_%=:\n\t"
        "mbarrier.try_wait.parity.acquire.cta.shared::cta.b64 P, [%0], %1, 10000000;\n\t"
        "@P bra.uni D_%=;\n\t"
        "bra.uni W_%=;\n\t"
        "D_%=:\n\t}"
        :: "r"(mbar), "r"(parity) : "memory");
}
__device__ __forceinline__ void tma2d(uint32_t saddr, const CUtensorMap* tm,
                                      int cx, int cy, uint32_t mbar) {
    asm volatile(
        "cp.async.bulk.tensor.2d.shared::cta.global.tile.mbarrier::complete_tx::bytes "
        "[%0], [%1, {%2, %3}], [%4];"
        :: "r"(saddr), "l"(tm), "r"(cx), "r"(cy), "r"(mbar) : "memory");
}
__device__ __forceinline__ uint32_t pack2(float a, float b) {
    __nv_bfloat162 h = __floats2bfloat162_rn(a, b);
    return *(uint32_t*)&h;
}

// ---------------- zero fill ----------------------------------------------------
__global__ void zero_kernel(float* __restrict__ p, int n) {
    int i = blockIdx.x * blockDim.x + threadIdx.x;
    if (i < n) p[i] = 0.0f;
}

// ---------------- fp32 -> bf16 conversion ---------------------------------------
__global__ __launch_bounds__(256) void convert_f2b(
    const float* __restrict__ src, __nv_bfloat16* __restrict__ dst, int n4)
{
    int i = blockIdx.x * 256 + threadIdx.x;
    if (i >= n4) return;
    float4 v = ((const float4*)src)[i];
    uint2 o;
    o.x = pack2(v.x, v.y);
    o.y = pack2(v.z, v.w);
    ((uint2*)dst)[i] = o;
}

// ---------------- convert all weights to bf16 ------------------------------------
struct WSrc { const float* p[9]; };
#define WO0 0
#define WO1 65536
#define WO2 131072
#define WO3 196608
#define WO4 458752
#define WO5 655360
#define WO6 851968
#define WO7 917504
#define WO8 983040
__global__ __launch_bounds__(256) void round_weights(WSrc ws) {
    int f = (blockIdx.x * 256 + threadIdx.x) * 4;
    if (f >= 1048576) return;
    const float* sp; int base;
    if      (f < WO1) { sp = ws.p[0]; base = WO0; }
    else if (f < WO2) { sp = ws.p[1]; base = WO1; }
    else if (f < WO3) { sp = ws.p[2]; base = WO2; }
    else if (f < WO4) { sp = ws.p[3]; base = WO3; }
    else if (f < WO5) { sp = ws.p[4]; base = WO4; }
    else if (f < WO6) { sp = ws.p[5]; base = WO5; }
    else if (f < WO7) { sp = ws.p[6]; base = WO6; }
    else if (f < WO8) { sp = ws.p[7]; base = WO7; }
    else              { sp = ws.p[8]; base = WO8; }
    float4 v = *(const float4*)(sp + (f - base));
    uint2 o;
    o.x = pack2(v.x, v.y);
    o.y = pack2(v.z, v.w);
    *(uint2*)(g_wb + f) = o;
}

// ---------------- TMA-fed bf16 GEMM: C[M,256] = [ssp](A[M,K] @ W^T) [+R] --------
// Block 128x128 (grid.x = 2 n-blocks), 8 warps, warp tile 32x64 (4m x 2n).
// TBK=64 bf16 (128B rows, SW128), 3-stage TMA pipeline, mma.sync bf16 m16n8k16.
// ACT: ssp. ADD: +R (fp32). OUTBF: store bf16, else fp32. SC=2: n->graph scatter.
#define STG_BYTES 32768u
#define SMEMSZ (3 * 32768 + 1024)

template <int ACT, int ADD, int OUTBF, int SC>
__global__ __launch_bounds__(256, 2) void gemm_b(
    const __grid_constant__ CUtensorMap tmA,
    const __grid_constant__ CUtensorMap tmW,
    const float* __restrict__ R, void* __restrict__ Cout,
    int M, int K, const int* __restrict__ batch)
{
    extern __shared__ float dsm[];
    __shared__ __align__(8) uint64_t mbar_s[3];
    uint32_t smb = (uint32_t)__cvta_generic_to_shared(dsm);
    smb = (smb + 1023u) & ~1023u;
    const uint32_t mb = (uint32_t)__cvta_generic_to_shared(mbar_s);

    const int tid = threadIdx.x;
    const int m0 = blockIdx.y * 128;
    const int n0 = blockIdx.x * 128;

    if (tid == 0) {
        mbar_init(mb, 1); mbar_init(mb + 8, 1); mbar_init(mb + 16, 1);
    }
    __syncthreads();

    const int KT = K / 64;       // 64 bf16 per stage row (128B)
    auto issue = [&](int kt, int s) {
        uint32_t base = smb + (uint32_t)s * STG_BYTES;
        mbar_expect(mb + s * 8, STG_BYTES);
        tma2d(base, &tmA, kt * 64, m0, mb + s * 8);
        tma2d(base + 16384u, &tmW, kt * 64, n0, mb + s * 8);
    };
    if (tid == 0) {
        int pre = KT < 3 ? KT : 3;
        for (int i = 0; i < pre; i++) issue(i, i);
    }

    // ---- fragment addressing (SW128: 16B chunk ^= row&7 within 128B rows)
    const int lane = tid & 31, warp = tid >> 5;
    const int wm = (warp & 3) * 32;
    const int wn = (warp >> 2) * 64;
    const int gid = lane >> 2, tig = lane & 3;
    const int hA = (lane >> 4) & 1;
    const int hB = (lane >> 3) & 1;
    const int arow = wm + (lane & 15);
    const int brow = wn + ((lane >> 4) & 1) * 8 + (lane & 7);
    const uint32_t aAddr = smb + (uint32_t)(arow * 128);
    const uint32_t bAddr = smb + 16384u + (uint32_t)(brow * 128);
    uint32_t cA[4], cB[4];
#pragma unroll
    for (int ks = 0; ks < 4; ks++) {
        cA[ks] = (uint32_t)(((ks * 2 + hA) ^ (arow & 7)) << 4);
        cB[ks] = (uint32_t)(((ks * 2 + hB) ^ (brow & 7)) << 4);
    }

    float acc[2][8][4];
#pragma unroll
    for (int mt = 0; mt < 2; mt++)
#pragma unroll
        for (int nt = 0; nt < 8; nt++)
#pragma unroll
            for (int i = 0; i < 4; i++) acc[mt][nt][i] = 0.0f;

    for (int kt = 0; kt < KT; kt++) {
        const int s = kt % 3;
        mbar_wait(mb + s * 8, (uint32_t)((kt / 3) & 1));
        const uint32_t so = (uint32_t)s * STG_BYTES;

#pragma unroll
        for (int ks = 0; ks < 4; ks++) {       // 4 x k16 per 128B row
            uint32_t a[2][4];
#pragma unroll
            for (int mt = 0; mt < 2; mt++)
                ldsm4(a[mt][0], a[mt][1], a[mt][2], a[mt][3],
                      aAddr + so + (uint32_t)(mt * 2048) + cA[ks]);
            uint32_t b0[8], b1[8];
#pragma unroll
            for (int g = 0; g < 4; g++)
                ldsm4(b0[2 * g], b1[2 * g], b0[2 * g + 1], b1[2 * g + 1],
                      bAddr + so + (uint32_t)(g * 2048) + cB[ks]);
#pragma unroll
            for (int mt = 0; mt < 2; mt++)
#pragma unroll
                for (int nt = 0; nt < 8; nt++)
                    mma_bf16(acc[mt][nt], a[mt][0], a[mt][1], a[mt][2],
                             a[mt][3], b0[nt], b1[nt]);
        }
        __syncthreads();
        if (tid == 0 && kt + 3 < KT) issue(kt + 3, s);
    }

    // ---- epilogue
    int* sbt = (int*)dsm;
    if (SC == 2) {
        if (tid < 128) sbt[tid] = batch[min(m0 + tid, M - 1)];
        __syncthreads();
    }

#pragma unroll
    for (int mt = 0; mt < 2; mt++) {
#pragma unroll
        for (int half = 0; half < 2; half++) {
            int r = wm + mt * 16 + half * 8 + gid;
            int gr = m0 + r;
            if (gr >= M) continue;
#pragma unroll
            for (int nt = 0; nt < 8; nt++) {
                int col = n0 + wn + nt * 8 + tig * 2;
                float o0 = acc[mt][nt][half * 2 + 0];
                float o1 = acc[mt][nt][half * 2 + 1];
                if (ACT) { o0 = ssp(o0); o1 = ssp(o1); }
                if (SC == 2) {
                    atomicAdd(&g_small[OFF_N2G + sbt[r] * 256 + col], o0);
                    atomicAdd(&g_small[OFF_N2G + sbt[r] * 256 + col + 1], o1);
                }
                if (ADD) {
                    float2 rv = *(const float2*)&R[(size_t)gr * 256 + col];
                    o0 += rv.x; o1 += rv.y;
                }
                if (OUTBF) {
                    ((uint32_t*)Cout)[((size_t)gr * 256 + col) >> 1] = pack2(o0, o1);
                } else {
                    *(float2*)&((float*)Cout)[(size_t)gr * 256 + col] = make_float2(o0, o1);
                }
            }
            if (SC == 2 && blockIdx.x == 0 && wn == 0 && tig == 0)
                atomicAdd(&g_small[OFF_GCN + sbt[r]], 1.0f);
        }
    }
}

// ---------------- edge combine: emid = ssp(P1[s]+P2[d]+P3[e]+P4[b]) + scatter ---
__global__ __launch_bounds__(256) void combine_edge(
    const int* __restrict__ src, const int* __restrict__ dst,
    const int* __restrict__ batch)
{
    int e = blockIdx.x * 4 + (threadIdx.x >> 6);
    int t = threadIdx.x & 63;
    int s = src[e], d = dst[e], b = batch[s];
    float4 p1 = ((const float4*)g_p1)[(size_t)s * 64 + t];
    float4 p2 = ((const float4*)g_p2)[(size_t)d * 64 + t];
    float4 p3 = ((const float4*)g_p3)[(size_t)e * 64 + t];
    float4 p4 = ((const float4*)g_p4)[(size_t)b * 64 + t];
    float o0 = ssp(p1.x + p2.x + p3.x + p4.x);
    float o1 = ssp(p1.y + p2.y + p3.y + p4.y);
    float o2 = ssp(p1.z + p2.z + p3.z + p4.z);
    float o3 = ssp(p1.w + p2.w + p3.w + p4.w);
    red4(&g_e2n[(size_t)d * 256 + t * 4], o0, o1, o2, o3);
    red4(&g_small[OFF_E2G + b * 256 + t * 4], o0, o1, o2, o3);
    if (t == 0) {
        atomicAdd(&g_small[OFF_NCNT + d], 1.0f);
        atomicAdd(&g_small[OFF_GCE + b], 1.0f);
    }
    uint2 ov;
    ov.x = pack2(o0, o1);
    ov.y = pack2(o2, o3);
    ((uint2*)g_bemid)[(size_t)e * 64 + t] = ov;
}

// ---------------- node_in = [n1, e2n_mean, g1[batch]] (bf16) --------------------
__global__ __launch_bounds__(192) void build_node_in(const int* __restrict__ batch)
{
    int v = blockIdx.x;
    int t = threadIdx.x;
    int seg = t / 64, w = t % 64;
    uint2 val;
    if (seg == 0) {
        val = ((const uint2*)g_bn1)[(size_t)v * 64 + w];
    } else if (seg == 1) {
        float inv = 1.0f / fmaxf(g_small[OFF_NCNT + v], 1.0f);
        float4 sv = ((const float4*)g_e2n)[(size_t)v * 64 + w];
        val.x = pack2(sv.x * inv, sv.y * inv);
        val.y = pack2(sv.z * inv, sv.w * inv);
    } else {
        int b = batch[v];
        val = ((const uint2*)g_bg1)[(size_t)b * 64 + w];
    }
    ((uint2*)g_bnin)[(size_t)v * 192 + t] = val;
}

// ---------------- glob_in = [n2g_mean, e2g_mean, g1] (bf16) ---------------------
__global__ __launch_bounds__(192) void build_glob_in()
{
    int gi = blockIdx.x;
    int t = threadIdx.x;
    int seg = t / 64, w = t % 64;
    uint2 val;
    if (seg == 0) {
        float inv = 1.0f / fmaxf(g_small[OFF_GCN + gi], 1.0f);
        float4 sv = *(const float4*)&g_small[OFF_N2G + gi * 256 + w * 4];
        val.x = pack2(sv.x * inv, sv.y * inv);
        val.y = pack2(sv.z * inv, sv.w * inv);
    } else if (seg == 1) {
        float inv = 1.0f / fmaxf(g_small[OFF_GCE + gi], 1.0f);
        float4 sv = *(const float4*)&g_small[OFF_E2G + gi * 256 + w * 4];
        val.x = pack2(sv.x * inv, sv.y * inv);
        val.y = pack2(sv.z * inv, sv.w * inv);
    } else {
        val = ((const uint2*)g_bg1)[(size_t)gi * 64 + w];
    }
    ((uint2*)g_bgin)[(size_t)gi * 192 + t] = val;
}

// ---------------- host side -------------------------------------------------------
template <typename T>
static T* sym(const void* symbol) {
    void* p = nullptr;
    cudaGetSymbolAddress(&p, symbol);
    return (T*)p;
}

typedef CUresult (*PFN_encode)(
    CUtensorMap*, CUtensorMapDataType, cuuint32_t, void*,
    const cuuint64_t*, const cuuint64_t*, const cuuint32_t*, const cuuint32_t*,
    CUtensorMapInterleave, CUtensorMapSwizzle, CUtensorMapL2promotion,
    CUtensorMapFloatOOBfill);

static void enc(PFN_encode fn, CUtensorMap* m, const void* base,
                unsigned long long kElems, unsigned long long rows,
                unsigned long long rowStrideBytes) {
    cuuint64_t dims[2] = {kElems, rows};
    cuuint64_t st[1] = {rowStrideBytes};
    cuuint32_t box[2] = {64u, 128u};   // 64 bf16 = 128B per row
    cuuint32_t es[2] = {1u, 1u};
    fn(m, CU_TENSOR_MAP_DATA_TYPE_BFLOAT16, 2, (void*)base, dims, st, box, es,
       CU_TENSOR_MAP_INTERLEAVE_NONE, CU_TENSOR_MAP_SWIZZLE_128B,
       CU_TENSOR_MAP_L2_PROMOTION_L2_128B, CU_TENSOR_MAP_FLOAT_OOB_FILL_NONE);
}

extern "C" void kernel_launch(void* const* d_in, const int* in_sizes, int n_in,
                              void* d_out, int out_size) {
    const float* node_feats = (const float*)d_in[0];
    const float* edge_feats = (const float*)d_in[1];
    const float* glob_feats = (const float*)d_in[2];
    const int*   edge_index = (const int*)d_in[3];
    const int*   batch      = (const int*)d_in[4];

    const int* src = edge_index;
    const int* dst = edge_index + NE;

    float* out = (float*)d_out;
    float* out_n = out;
    float* out_e = out + (size_t)NN * 256;
    float* out_g = out + (size_t)(NN + NE) * 256;

    __nv_bfloat16* p_bnode = sym<__nv_bfloat16>(g_bnode);
    __nv_bfloat16* p_bedge = sym<__nv_bfloat16>(g_bedge);
    __nv_bfloat16* p_bglob = sym<__nv_bfloat16>(g_bglob);
    __nv_bfloat16* p_bn1   = sym<__nv_bfloat16>(g_bn1);
    __nv_bfloat16* p_be1   = sym<__nv_bfloat16>(g_be1);
    __nv_bfloat16* p_bg1   = sym<__nv_bfloat16>(g_bg1);
    __nv_bfloat16* p_bnin  = sym<__nv_bfloat16>(g_bnin);
    __nv_bfloat16* p_bgin  = sym<__nv_bfloat16>(g_bgin);
    __nv_bfloat16* p_bnmid = sym<__nv_bfloat16>(g_bnmid);
    __nv_bfloat16* p_bemid = sym<__nv_bfloat16>(g_bemid);
    __nv_bfloat16* p_bgmid = sym<__nv_bfloat16>(g_bgmid);
    __nv_bfloat16* p_wb    = sym<__nv_bfloat16>(g_wb);
    float* p_p1 = sym<float>(g_p1);
    float* p_p2 = sym<float>(g_p2);
    float* p_p3 = sym<float>(g_p3);
    float* p_p4 = sym<float>(g_p4);
    float* p_e2n = sym<float>(g_e2n);
    float* p_small = sym<float>(g_small);

    PFN_encode encfn = nullptr;
    {
        void* fp = nullptr;
        cudaDriverEntryPointQueryResult qr;
        cudaGetDriverEntryPoint("cuTensorMapEncodeTiled", &fp,
                                cudaEnableDefault, &qr);
        encfn = (PFN_encode)fp;
    }

    // ---- tensormaps (all bf16)
    CUtensorMap mA_node, mA_edge, mA_glob, mA_n1, mA_e1, mA_g1;
    CUtensorMap mA_nin, mA_gin, mA_nmid, mA_emid, mA_gmid;
    enc(encfn, &mA_node, p_bnode, 256, NN, 512);
    enc(encfn, &mA_edge, p_bedge, 256, NE, 512);
    enc(encfn, &mA_glob, p_bglob, 256, NG, 512);
    enc(encfn, &mA_n1, p_bn1, 256, NN, 512);
    enc(encfn, &mA_e1, p_be1, 256, NE, 512);
    enc(encfn, &mA_g1, p_bg1, 256, NG, 512);
    enc(encfn, &mA_nin, p_bnin, 768, NN, 1536);
    enc(encfn, &mA_gin, p_bgin, 768, NG, 1536);
    enc(encfn, &mA_nmid, p_bnmid, 256, NN, 512);
    enc(encfn, &mA_emid, p_bemid, 256, NE, 512);
    enc(encfn, &mA_gmid, p_bgmid, 256, NG, 512);

    CUtensorMap mW_n1, mW_e1, mW_g1, mW_p1, mW_p2, mW_p3, mW_p4;
    CUtensorMap mW_nmlp, mW_gmlp, mW_n2, mW_e2, mW_g2;
    enc(encfn, &mW_n1, p_wb + WO0, 256, 256, 512);
    enc(encfn, &mW_e1, p_wb + WO1, 256, 256, 512);
    enc(encfn, &mW_g1, p_wb + WO2, 256, 256, 512);
    enc(encfn, &mW_p1, p_wb + WO3 + 0,   256, 256, 2048);
    enc(encfn, &mW_p2, p_wb + WO3 + 256, 256, 256, 2048);
    enc(encfn, &mW_p3, p_wb + WO3 + 512, 256, 256, 2048);
    enc(encfn, &mW_p4, p_wb + WO3 + 768, 256, 256, 2048);
    enc(encfn, &mW_nmlp, p_wb + WO4, 768, 256, 1536);
    enc(encfn, &mW_gmlp, p_wb + WO5, 768, 256, 1536);
    enc(encfn, &mW_n2, p_wb + WO6, 256, 256, 512);
    enc(encfn, &mW_e2, p_wb + WO7, 256, 256, 512);
    enc(encfn, &mW_g2, p_wb + WO8, 256, 256, 512);

    cudaFuncSetAttribute(gemm_b<1,0,1,0>, cudaFuncAttributeMaxDynamicSharedMemorySize, SMEMSZ);
    cudaFuncSetAttribute(gemm_b<0,0,0,0>, cudaFuncAttributeMaxDynamicSharedMemorySize, SMEMSZ);
    cudaFuncSetAttribute(gemm_b<1,0,1,2>, cudaFuncAttributeMaxDynamicSharedMemorySize, SMEMSZ);
    cudaFuncSetAttribute(gemm_b<1,1,0,0>, cudaFuncAttributeMaxDynamicSharedMemorySize, SMEMSZ);

    const int BN_N = (NN + 127) / 128;
    const int BN_E = (NE + 127) / 128;

    // zero scatter accumulators
    zero_kernel<<<(NN * 256 + 255) / 256, 256>>>(p_e2n, NN * 256);
    zero_kernel<<<(SMALL_N + 255) / 256, 256>>>(p_small, SMALL_N);

    // convert weights + raw inputs to bf16
    WSrc ws;
    for (int i = 0; i < 9; i++) ws.p[i] = (const float*)d_in[5 + i];
    round_weights<<<1024, 256>>>(ws);
    convert_f2b<<<(NN * 64 + 255) / 256, 256>>>(node_feats, p_bnode, NN * 64);
    convert_f2b<<<(NE * 64 + 255) / 256, 256>>>(edge_feats, p_bedge, NE * 64);
    convert_f2b<<<(NG * 64 + 255) / 256, 256>>>(glob_feats, p_bglob, NG * 64);

    // stage 1: input projections + ssp -> bf16
    gemm_b<1,0,1,0><<<dim3(2, BN_N), 256, SMEMSZ>>>(mA_node, mW_n1, nullptr, p_bn1, NN, 256, nullptr);
    gemm_b<1,0,1,0><<<dim3(2, BN_E), 256, SMEMSZ>>>(mA_edge, mW_e1, nullptr, p_be1, NE, 256, nullptr);
    gemm_b<1,0,1,0><<<dim3(2, 1),    256, SMEMSZ>>>(mA_glob, mW_g1, nullptr, p_bg1, NG, 256, nullptr);

    // EdgeModel decomposed: P1..P4 partials (fp32, no activation)
    gemm_b<0,0,0,0><<<dim3(2, BN_N), 256, SMEMSZ>>>(mA_n1, mW_p1, nullptr, p_p1, NN, 256, nullptr);
    gemm_b<0,0,0,0><<<dim3(2, BN_N), 256, SMEMSZ>>>(mA_n1, mW_p2, nullptr, p_p2, NN, 256, nullptr);
    gemm_b<0,0,0,0><<<dim3(2, BN_E), 256, SMEMSZ>>>(mA_e1, mW_p3, nullptr, p_p3, NE, 256, nullptr);
    gemm_b<0,0,0,0><<<dim3(2, 1),    256, SMEMSZ>>>(mA_g1, mW_p4, nullptr, p_p4, NG, 256, nullptr);

    // combine + ssp + scatter (e2n, e2g, counts) + emid(bf16)
    combine_edge<<<NE / 4, 256>>>(src, dst, batch);

    // NodeModel
    build_node_in<<<NN, 192>>>(batch);
    gemm_b<1,0,1,2><<<dim3(2, BN_N), 256, SMEMSZ>>>(mA_nin, mW_nmlp, nullptr, p_bnmid, NN, 768, batch);

    // GlobalModel
    build_glob_in<<<NG, 192>>>();
    gemm_b<1,0,1,0><<<dim3(2, 1), 256, SMEMSZ>>>(mA_gin, mW_gmlp, nullptr, p_bgmid, NG, 768, nullptr);

    // output projections + ssp + residual (fp32 outputs)
    gemm_b<1,1,0,0><<<dim3(2, BN_N), 256, SMEMSZ>>>(mA_nmid, mW_n2, node_feats, out_n, NN, 256, nullptr);
    gemm_b<1,1,0,0><<<dim3(2, BN_E), 256, SMEMSZ>>>(mA_emid, mW_e2, edge_feats, out_e, NE, 256, nullptr);
    gemm_b<1,1,0,0><<<dim3(2, 1),    256, SMEMSZ>>>(mA_gmid, mW_g2, glob_feats, out_g, NG, 256, nullptr);
}